// round 3
// baseline (speedup 1.0000x reference)
#include <cuda_runtime.h>
#include <cstdint>

// TitansMemory: B=16, L=8192, DK=DV=128.
// 2048 independent (b,v) row-chains.
// R2: 2 rows per warp (16-lane groups, 8 floats/lane), 4-level butterfly,
// exponentially rescaled state (W = c1^t * What, m = beta^t * mhat) so the
// per-step update is 5 f32x2 ops per register pair and all decay constants
// are compile-time immediates. y_t = c1^{t+1} * (What_post . q).

#define CSTEPS 16
#define L_SEQ  8192
#define NCH    (L_SEQ / CSTEPS)
#define DK     128

using ull = unsigned long long;

__host__ __device__ constexpr double dpow(double b, int n) {
    double r = 1.0; for (int i = 0; i < n; ++i) r *= b; return r;
}

__device__ __forceinline__ ull pk(float lo, float hi) {
    ull r; asm("mov.b64 %0,{%1,%2};" : "=l"(r) : "f"(lo), "f"(hi)); return r;
}
__device__ __forceinline__ float hadd2(ull p) {
    float lo, hi; asm("mov.b64 {%0,%1},%2;" : "=f"(lo), "=f"(hi) : "l"(p));
    return lo + hi;
}
__device__ __forceinline__ ull mul2(ull a, ull b) {
    ull d; asm("mul.rn.f32x2 %0,%1,%2;" : "=l"(d) : "l"(a), "l"(b)); return d;
}
__device__ __forceinline__ ull fma2(ull a, ull b, ull c) {
    ull d; asm("fma.rn.f32x2 %0,%1,%2,%3;" : "=l"(d) : "l"(a), "l"(b), "l"(c)); return d;
}
__device__ __forceinline__ ull add2(ull a, ull b) {
    ull d; asm("add.rn.f32x2 %0,%1,%2;" : "=l"(d) : "l"(a), "l"(b)); return d;
}
__device__ __forceinline__ unsigned su32(const void* p) {
    return (unsigned)__cvta_generic_to_shared(p);
}
__device__ __forceinline__ void cp16(unsigned s, const void* g) {
    asm volatile("cp.async.cg.shared.global [%0],[%1],16;" :: "r"(s), "l"(g));
}
__device__ __forceinline__ void cp4(unsigned s, const void* g) {
    asm volatile("cp.async.ca.shared.global [%0],[%1],4;" :: "r"(s), "l"(g));
}
__device__ __forceinline__ void cp_commit() {
    asm volatile("cp.async.commit_group;" ::: "memory");
}
__device__ __forceinline__ void cp_wait_all() {
    asm volatile("cp.async.wait_group 0;" ::: "memory");
}

__global__ __launch_bounds__(256, 1)
void titans_kernel(const float* __restrict__ Q,
                   const float* __restrict__ K,
                   const float* __restrict__ V,
                   float* __restrict__ Y) {
    __shared__ float k_buf[2][CSTEPS][DK];
    __shared__ float q_buf[2][CSTEPS][DK];
    __shared__ float v_buf[2][16][CSTEPS];   // [row][step]
    __shared__ float y_buf[2][CSTEPS][16];   // [step][row]

    const int tid  = threadIdx.x;
    const int w    = tid >> 5;               // warp 0..7
    const int lane = tid & 31;
    const int g    = lane & 15;              // position within 16-lane group
    const int half = lane >> 4;              // 0/1 -> which row of this warp
    const int row  = (w << 1) + half;        // 0..15 within CTA

    const int b     = blockIdx.x >> 3;       // 16 batches
    const int vbase = (blockIdx.x & 7) << 4; // 8 CTAs x 16 rows per batch

    const size_t base = (size_t)b * L_SEQ * DK;
    const float* gk = K + base;
    const float* gq = Q + base;
    const float* gv = V + base;
    float*       gy = Y + base;

    // rescaled state: lane owns What[row, 8g..8g+7], mhat same. 4 f32x2 pairs.
    ull W0 = 0, W1 = 0, W2 = 0, W3 = 0;
    ull M0 = 0, M1 = 0, M2 = 0, M3 = 0;

    // ---- preload chunk 0 ----
    {
        #pragma unroll
        for (int u = 0; u < 2; ++u) {
            cp16(su32(&k_buf[0][0][0]) + (u * 256 + tid) * 16, gk + (u * 256 + tid) * 4);
            cp16(su32(&q_buf[0][0][0]) + (u * 256 + tid) * 16, gq + (u * 256 + tid) * 4);
        }
        {
            int j = tid & 15, i = tid >> 4;
            cp4(su32(&v_buf[0][j][i]), gv + (size_t)i * DK + vbase + j);
        }
        cp_commit();
        cp_wait_all();
        __syncthreads();
    }

    for (int chunk = 0; chunk < NCH; ++chunk) {
        const int cur = chunk & 1;
        const int t0  = chunk * CSTEPS;

        // stage this warp's row-v values into registers (16-way broadcast reads)
        float vreg[CSTEPS];
        #pragma unroll
        for (int jj = 0; jj < 4; ++jj)
            *(float4*)&vreg[jj * 4] = *(const float4*)&v_buf[cur][row][jj * 4];

        // prefetch next chunk
        if (chunk + 1 < NCH) {
            const int nb = cur ^ 1;
            const size_t nt = (size_t)(t0 + CSTEPS) * DK;
            #pragma unroll
            for (int u = 0; u < 2; ++u) {
                cp16(su32(&k_buf[nb][0][0]) + (u * 256 + tid) * 16, gk + nt + (u * 256 + tid) * 4);
                cp16(su32(&q_buf[nb][0][0]) + (u * 256 + tid) * 16, gq + nt + (u * 256 + tid) * 4);
            }
            {
                int j = tid & 15, i = tid >> 4;
                cp4(su32(&v_buf[nb][j][i]), gv + nt + (size_t)i * DK + vbase + j);
            }
        }
        cp_commit();

        // ---- 16 sequential steps, fully unrolled (constants become immediates) ----
        #pragma unroll
        for (int i = 0; i < CSTEPS; ++i) {
            const float4 ka = *(const float4*)&k_buf[cur][i][g * 8];
            const float4 kb = *(const float4*)&k_buf[cur][i][g * 8 + 4];
            const float4 qa = *(const float4*)&q_buf[cur][i][g * 8];
            const float4 qb = *(const float4*)&q_buf[cur][i][g * 8 + 4];

            const ull k0 = pk(ka.x, ka.y), k1 = pk(ka.z, ka.w);
            const ull k2 = pk(kb.x, kb.y), k3 = pk(kb.z, kb.w);
            const ull q0 = pk(qa.x, qa.y), q1 = pk(qa.z, qa.w);
            const ull q2 = pk(qb.x, qb.y), q3 = pk(qb.z, qb.w);

            // dot: What_pre . k   (tree)
            const ull da = fma2(k0, W0, mul2(k1, W1));
            const ull db = fma2(k2, W2, mul2(k3, W3));
            float D1 = hadd2(add2(da, db));
            #pragma unroll
            for (int off = 8; off; off >>= 1)
                D1 += __shfl_xor_sync(0xffffffffu, D1, off);

            // compile-time step constants
            const float CPi = (float)dpow(0.98, i);                    // c1^i
            const float Ai  = (float)(-0.02 / dpow(0.98, i + 1));      // -lr*c2*c1^-(i+1)
            const float Bi  = (float)(0.2   / dpow(0.9,  i + 1));      // c2*beta^-(i+1)
            const float S1i = (float)(-0.1  * dpow(0.9 / 0.98, i + 1));// -lr*(b/c1)^(i+1)
            const float CYi = (float)dpow(0.98, i + 1);                // c1^(i+1)

            const float r  = fmaf(CPi, D1, -vreg[i]);
            const ull  a2 = pk(Ai * r, Ai * r);
            const ull  b2 = pk(Bi * r, Bi * r);
            const ull  s2 = pk(S1i, S1i);

            // What += s1*mhat + a*k ;  mhat += b*k
            W0 = fma2(s2, M0, W0); W0 = fma2(a2, k0, W0); M0 = fma2(b2, k0, M0);
            W1 = fma2(s2, M1, W1); W1 = fma2(a2, k1, W1); M1 = fma2(b2, k1, M1);
            W2 = fma2(s2, M2, W2); W2 = fma2(a2, k2, W2); M2 = fma2(b2, k2, M2);
            W3 = fma2(s2, M3, W3); W3 = fma2(a2, k3, W3); M3 = fma2(b2, k3, M3);

            // y = c1^(i+1) * (What_post . q)   (off the recurrence critical path)
            const ull ea = fma2(q0, W0, mul2(q1, W1));
            const ull eb = fma2(q2, W2, mul2(q3, W3));
            float D2 = hadd2(add2(ea, eb));
            #pragma unroll
            for (int off = 8; off; off >>= 1)
                D2 += __shfl_xor_sync(0xffffffffu, D2, off);
            if (g == 0)
                y_buf[cur][i][row] = CYi * D2;
        }

        // rescale state back to chunk-local frame
        {
            const ull c16 = pk((float)dpow(0.98, CSTEPS), (float)dpow(0.98, CSTEPS));
            const ull b16 = pk((float)dpow(0.9,  CSTEPS), (float)dpow(0.9,  CSTEPS));
            W0 = mul2(c16, W0); W1 = mul2(c16, W1); W2 = mul2(c16, W2); W3 = mul2(c16, W3);
            M0 = mul2(b16, M0); M1 = mul2(b16, M1); M2 = mul2(b16, M2); M3 = mul2(b16, M3);
        }

        cp_wait_all();
        __syncthreads();

        // write back this chunk's outputs
        {
            int i = tid >> 4, j = tid & 15;
            gy[(size_t)(t0 + i) * DK + vbase + j] = y_buf[cur][i][j];
        }
    }
}

extern "C" void kernel_launch(void* const* d_in, const int* in_sizes, int n_in,
                              void* d_out, int out_size) {
    const float* Q = (const float*)d_in[0];
    const float* K = (const float*)d_in[1];
    const float* V = (const float*)d_in[2];
    float* Y = (float*)d_out;
    (void)in_sizes; (void)n_in; (void)out_size;
    titans_kernel<<<128, 256>>>(Q, K, V, Y);
}